// round 5
// baseline (speedup 1.0000x reference)
#include <cuda_runtime.h>
#include <cuda_bf16.h>
#include <cstdint>

// ===========================================================================
// CrossModalAttention collapses analytically:
//   fa[b,s,:] constant over s => K_a, V_a constant over t
//   => softmax uniform => attn_out[b,s,:] == va[b,:]
//   => out = text @ Wt + bt + va[b]      (one real GEMM)
// GEMM on tensor cores via bf16x3 fp32 emulation (Ah*Bh + Ah*Bl + Al*Bh).
// Round 5: 2 CTAs/SM (256 thr, 128x128 tile), 3-stage multistage with KT=32,
// SW64 smem, one sync per chunk, loads issued ahead of compute.
// ===========================================================================

#define BATCH 8
#define SEQ   2048
#define DM    768
#define DAUD  16
#define M_TOT (BATCH * SEQ)

__device__ float g_va[BATCH * DM];
__device__ __nv_bfloat16 g_Ah[M_TOT * DM];
__device__ __nv_bfloat16 g_Al[M_TOT * DM];
__device__ __nv_bfloat16 g_Bh[DM * DM];     // Wt transposed: [N, K]
__device__ __nv_bfloat16 g_Bl[DM * DM];

// ------------------------------ helpers ------------------------------------
__device__ __forceinline__ uint32_t smem_u32(const void* p) {
    uint32_t r;
    asm("{ .reg .u64 t; cvta.to.shared.u64 t, %1; cvt.u32.u64 %0, t; }"
        : "=r"(r) : "l"(p));
    return r;
}

#define SWZ64(o) ((o) ^ (((o) >> 3) & 0x30))

__device__ __forceinline__ void cpasync16(uint32_t dst, const void* src) {
    asm volatile("cp.async.cg.shared.global [%0], [%1], 16;"
                 :: "r"(dst), "l"(src));
}

__device__ __forceinline__ void ldsm4(uint32_t* r, uint32_t addr) {
    asm volatile("ldmatrix.sync.aligned.m8n8.x4.shared.b16 {%0,%1,%2,%3}, [%4];"
                 : "=r"(r[0]), "=r"(r[1]), "=r"(r[2]), "=r"(r[3])
                 : "r"(addr));
}

__device__ __forceinline__ void mma16816(float* d,
                                         const uint32_t* a,
                                         uint32_t b0, uint32_t b1) {
    asm volatile(
        "mma.sync.aligned.m16n8k16.row.col.f32.bf16.bf16.f32 "
        "{%0,%1,%2,%3}, {%4,%5,%6,%7}, {%8,%9}, {%0,%1,%2,%3};"
        : "+f"(d[0]), "+f"(d[1]), "+f"(d[2]), "+f"(d[3])
        : "r"(a[0]), "r"(a[1]), "r"(a[2]), "r"(a[3]), "r"(b0), "r"(b1));
}

// ---------------------------------------------------------------------------
// Prep A: fp32 text -> (bf16 hi, bf16 lo), 8 elems/thread, 16B stores.
// ---------------------------------------------------------------------------
__global__ void split_text_kernel(const float* __restrict__ x) {
    size_t i = ((size_t)blockIdx.x * blockDim.x + threadIdx.x) * 8;
    float4 v0 = *(const float4*)(x + i);
    float4 v1 = *(const float4*)(x + i + 4);
    float f[8] = {v0.x, v0.y, v0.z, v0.w, v1.x, v1.y, v1.z, v1.w};
    __nv_bfloat162 h[4], l[4];
#pragma unroll
    for (int j = 0; j < 4; j++) {
        __nv_bfloat16 h0 = __float2bfloat16(f[2*j]);
        __nv_bfloat16 h1 = __float2bfloat16(f[2*j+1]);
        __nv_bfloat16 l0 = __float2bfloat16(f[2*j]   - __bfloat162float(h0));
        __nv_bfloat16 l1 = __float2bfloat16(f[2*j+1] - __bfloat162float(h1));
        h[j] = __halves2bfloat162(h0, h1);
        l[j] = __halves2bfloat162(l0, l1);
    }
    *(uint4*)(g_Ah + i) = *(const uint4*)h;
    *(uint4*)(g_Al + i) = *(const uint4*)l;
}

// ---------------------------------------------------------------------------
// Prep B: transpose + split Wt[K,N] -> g_Bh/g_Bl [N,K]
// ---------------------------------------------------------------------------
__global__ void wsplit_kernel(const float* __restrict__ W) {
    __shared__ float tile[32][33];
    int n0 = blockIdx.x * 32, k0 = blockIdx.y * 32;
    int tx = threadIdx.x, ty = threadIdx.y;
    for (int r = ty; r < 32; r += 8)
        tile[r][tx] = W[(size_t)(k0 + r) * DM + n0 + tx];
    __syncthreads();
    for (int r = ty; r < 32; r += 8) {
        float v = tile[tx][r];                 // = W[k0+tx][n0+r]
        __nv_bfloat16 h = __float2bfloat16(v);
        __nv_bfloat16 l = __float2bfloat16(v - __bfloat162float(h));
        g_Bh[(size_t)(n0 + r) * DM + k0 + tx] = h;
        g_Bl[(size_t)(n0 + r) * DM + k0 + tx] = l;
    }
}

// ---------------------------------------------------------------------------
// Prep C: va[b,:] = (acoustic[b,:] @ Wa + ba) @ Wv + bv
// ---------------------------------------------------------------------------
__global__ void va_kernel(const float* __restrict__ ac,
                          const float* __restrict__ Wa,
                          const float* __restrict__ ba,
                          const float* __restrict__ Wv,
                          const float* __restrict__ bv) {
    __shared__ float fa[DM];
    __shared__ float acs[DAUD];
    const int b = blockIdx.x;
    const int t = threadIdx.x;
    if (t < DAUD) acs[t] = ac[b * DAUD + t];
    __syncthreads();
    float v = ba[t];
#pragma unroll
    for (int k = 0; k < DAUD; k++) v += acs[k] * Wa[k * DM + t];
    fa[t] = v;
    __syncthreads();
    float o = bv[t];
    for (int e = 0; e < DM; e++) o += fa[e] * Wv[e * DM + t];
    g_va[b * DM + t] = o;
}

// ---------------------------------------------------------------------------
// GEMM: CTA tile 128x128, 256 threads (8 warps, 2x4), warp tile 64x32.
// KT=32 chunks, 3-stage multistage, SW64 smem rows (64B), 2 CTAs/SM.
// ---------------------------------------------------------------------------
#define BM      128
#define BN      128
#define KT      32
#define KSTEPS  2                          // 16 K per step
#define NCHUNK  (DM / KT)                  // 24
#define ROWB    64                         // bytes per smem row (KT*2)
#define TILEB   (BM * ROWB)                // 8 KB per tile buffer
#define STAGEB  (4 * TILEB)                // Ah, Al, Bh, Bl = 32 KB
#define NSTG    3
#define SMEM_DYN (NSTG * STAGEB + 1024)    // ~97 KB

__device__ __forceinline__ void load_chunk(uint32_t stg,
                                           const __nv_bfloat16* const* g0,
                                           int k0, int tid) {
#pragma unroll
    for (int t = 0; t < 4; t++) {
        const uint32_t tb = stg + t * TILEB;
#pragma unroll
        for (int j = 0; j < 2; j++) {
            const int q = tid + j * 256;          // 0..511
            const int row = q >> 2, cc = q & 3;   // 4x16B per 64B row
            cpasync16(tb + SWZ64(row * ROWB + cc * 16),
                      g0[t] + (size_t)row * DM + k0 + cc * 8);
        }
    }
    asm volatile("cp.async.commit_group;");
}

__global__ __launch_bounds__(256, 2)
void gemm_kernel(const float* __restrict__ bias, float* __restrict__ out) {
    extern __shared__ char dynsmem[];
    uint32_t base = smem_u32(dynsmem);
    base = (base + 1023u) & ~1023u;

    const int tid = threadIdx.x;
    const int wid = tid >> 5, lane = tid & 31;
    const int wm = wid >> 2, wn = wid & 3;    // 2x4 warp grid
    const int bn = blockIdx.x, bm = blockIdx.y;

    const __nv_bfloat16* g0[4] = {
        g_Ah + (size_t)bm * BM * DM,
        g_Al + (size_t)bm * BM * DM,
        g_Bh + (size_t)bn * BN * DM,
        g_Bl + (size_t)bn * BN * DM };

    float acc[4][4][4] = {};

    load_chunk(base + 0 * STAGEB, g0, 0 * KT, tid);
    load_chunk(base + 1 * STAGEB, g0, 1 * KT, tid);

    for (int c = 0; c < NCHUNK; ++c) {
        asm volatile("cp.async.wait_group 1;");
        __syncthreads();

        // Issue next load BEFORE compute: stage (c+2)%3 was last read at
        // chunk c-1, finished by the sync above.
        if (c + 2 < NCHUNK)
            load_chunk(base + ((c + 2) % NSTG) * STAGEB, g0, (c + 2) * KT, tid);
        else
            asm volatile("cp.async.commit_group;");

        const uint32_t stg = base + (c % NSTG) * STAGEB;
        const uint32_t Ah = stg,              Al = stg + TILEB;
        const uint32_t Bh = stg + 2 * TILEB,  Bl = Bh + TILEB;

#pragma unroll
        for (int ks = 0; ks < KSTEPS; ks++) {
            uint32_t ah[4][4], al[4][4];
            const int akb = ks * 32 + (lane >> 4) * 16;       // byte offset
#pragma unroll
            for (int mt = 0; mt < 4; mt++) {
                const int row = wm * 64 + mt * 16 + (lane & 15);
                const uint32_t off = SWZ64(row * ROWB + akb);
                ldsm4(ah[mt], Ah + off);
                ldsm4(al[mt], Al + off);
            }
            const int brow_base = wn * 32 + (lane & 7) + ((lane >> 4) << 3);
            const int bkb = ks * 32 + ((lane >> 3) & 1) * 16;
#pragma unroll
            for (int p = 0; p < 2; p++) {
                uint32_t bh[4], bl[4];
                const uint32_t off = SWZ64((brow_base + p * 16) * ROWB + bkb);
                ldsm4(bh, Bh + off);
                ldsm4(bl, Bl + off);
#pragma unroll
                for (int mt = 0; mt < 4; mt++) {
                    float* d0 = acc[mt][2 * p];
                    float* d1 = acc[mt][2 * p + 1];
                    mma16816(d0, ah[mt], bh[0], bh[1]);
                    mma16816(d1, ah[mt], bh[2], bh[3]);
                    mma16816(d0, ah[mt], bl[0], bl[1]);
                    mma16816(d1, ah[mt], bl[2], bl[3]);
                    mma16816(d0, al[mt], bh[0], bh[1]);
                    mma16816(d1, al[mt], bh[2], bh[3]);
                }
            }
        }
    }

    // Epilogue: out = acc + bias + va[b].  BM=128 -> bidx = bm >> 4.
    const int bidx = bm >> 4;
#pragma unroll
    for (int mt = 0; mt < 4; mt++) {
        const int r0 = bm * BM + wm * 64 + mt * 16 + (lane >> 2);
#pragma unroll
        for (int nt = 0; nt < 4; nt++) {
            const int col = bn * BN + wn * 32 + nt * 8 + (lane & 3) * 2;
            const float bv0 = bias[col]     + g_va[bidx * DM + col];
            const float bv1 = bias[col + 1] + g_va[bidx * DM + col + 1];
            float2 v0, v1;
            v0.x = acc[mt][nt][0] + bv0;  v0.y = acc[mt][nt][1] + bv1;
            v1.x = acc[mt][nt][2] + bv0;  v1.y = acc[mt][nt][3] + bv1;
            *(float2*)(out + (size_t)r0 * DM + col)       = v0;
            *(float2*)(out + (size_t)(r0 + 8) * DM + col) = v1;
        }
    }
}

// ---------------------------------------------------------------------------
// Launch. Input order: text, acoustic, Wt, bt, Wa, ba, Wq,bq, Wk,bk, Wv,bv
// ---------------------------------------------------------------------------
extern "C" void kernel_launch(void* const* d_in, const int* in_sizes, int n_in,
                              void* d_out, int out_size) {
    const float* text = (const float*)d_in[0];
    const float* ac   = (const float*)d_in[1];
    const float* Wt   = (const float*)d_in[2];
    const float* bt   = (const float*)d_in[3];
    const float* Wa   = (const float*)d_in[4];
    const float* ba   = (const float*)d_in[5];
    const float* Wv   = (const float*)d_in[10];
    const float* bv   = (const float*)d_in[11];
    float* out = (float*)d_out;

    cudaFuncSetAttribute(gemm_kernel,
                         cudaFuncAttributeMaxDynamicSharedMemorySize, SMEM_DYN);

    split_text_kernel<<<(M_TOT * DM) / 8 / 256, 256>>>(text);
    wsplit_kernel<<<dim3(DM / 32, DM / 32), dim3(32, 8)>>>(Wt);
    va_kernel<<<BATCH, DM>>>(ac, Wa, ba, Wv, bv);

    gemm_kernel<<<dim3(DM / BN, M_TOT / BM), 256, SMEM_DYN>>>(bt, out);
}

// round 7
// speedup vs baseline: 1.0669x; 1.0669x over previous
#include <cuda_runtime.h>
#include <cuda_bf16.h>
#include <cstdint>

// ===========================================================================
// CrossModalAttention collapses analytically:
//   fa[b,s,:] constant over s => K_a, V_a constant over t
//   => softmax uniform => attn_out[b,s,:] == va[b,:]
//   => out = text @ Wt + bt + va[b]      (one real GEMM)
// GEMM on tensor cores via bf16x3 fp32 emulation (Ah*Bh + Ah*Bl + Al*Bh).
// Round 6 (re-run; prior attempt hit an infra failure): round-4 config
// (CTA 256x128, 512 thr, KT=64, 2-stage) with product-major MMA ordering:
// same-accumulator reuse distance 2 -> 8 independent MMAs, breaking the
// HMMA RAW chain.
// ===========================================================================

#define BATCH 8
#define SEQ   2048
#define DM    768
#define DAUD  16
#define M_TOT (BATCH * SEQ)

__device__ float g_va[BATCH * DM];
__device__ __nv_bfloat16 g_Ah[M_TOT * DM];
__device__ __nv_bfloat16 g_Al[M_TOT * DM];
__device__ __nv_bfloat16 g_Bh[DM * DM];     // Wt transposed: [N, K]
__device__ __nv_bfloat16 g_Bl[DM * DM];

// ------------------------------ helpers ------------------------------------
__device__ __forceinline__ uint32_t smem_u32(const void* p) {
    uint32_t r;
    asm("{ .reg .u64 t; cvta.to.shared.u64 t, %1; cvt.u32.u64 %0, t; }"
        : "=r"(r) : "l"(p));
    return r;
}

#define SWZ(o) ((o) ^ (((o) >> 3) & 0x70))

__device__ __forceinline__ void cpasync16(uint32_t dst, const void* src) {
    asm volatile("cp.async.cg.shared.global [%0], [%1], 16;"
                 :: "r"(dst), "l"(src));
}

__device__ __forceinline__ void ldsm4(uint32_t* r, uint32_t addr) {
    asm volatile("ldmatrix.sync.aligned.m8n8.x4.shared.b16 {%0,%1,%2,%3}, [%4];"
                 : "=r"(r[0]), "=r"(r[1]), "=r"(r[2]), "=r"(r[3])
                 : "r"(addr));
}

__device__ __forceinline__ void mma16816(float* d,
                                         const uint32_t* a,
                                         uint32_t b0, uint32_t b1) {
    asm volatile(
        "mma.sync.aligned.m16n8k16.row.col.f32.bf16.bf16.f32 "
        "{%0,%1,%2,%3}, {%4,%5,%6,%7}, {%8,%9}, {%0,%1,%2,%3};"
        : "+f"(d[0]), "+f"(d[1]), "+f"(d[2]), "+f"(d[3])
        : "r"(a[0]), "r"(a[1]), "r"(a[2]), "r"(a[3]), "r"(b0), "r"(b1));
}

// ---------------------------------------------------------------------------
// Prep A: fp32 text -> (bf16 hi, bf16 lo), 8 elems/thread, 16B stores.
// ---------------------------------------------------------------------------
__global__ void split_text_kernel(const float* __restrict__ x) {
    size_t i = ((size_t)blockIdx.x * blockDim.x + threadIdx.x) * 8;
    float4 v0 = *(const float4*)(x + i);
    float4 v1 = *(const float4*)(x + i + 4);
    float f[8] = {v0.x, v0.y, v0.z, v0.w, v1.x, v1.y, v1.z, v1.w};
    __nv_bfloat162 h[4], l[4];
#pragma unroll
    for (int j = 0; j < 4; j++) {
        __nv_bfloat16 h0 = __float2bfloat16(f[2*j]);
        __nv_bfloat16 h1 = __float2bfloat16(f[2*j+1]);
        __nv_bfloat16 l0 = __float2bfloat16(f[2*j]   - __bfloat162float(h0));
        __nv_bfloat16 l1 = __float2bfloat16(f[2*j+1] - __bfloat162float(h1));
        h[j] = __halves2bfloat162(h0, h1);
        l[j] = __halves2bfloat162(l0, l1);
    }
    *(uint4*)(g_Ah + i) = *(const uint4*)h;
    *(uint4*)(g_Al + i) = *(const uint4*)l;
}

// ---------------------------------------------------------------------------
// Prep B: transpose + split Wt[K,N] -> g_Bh/g_Bl [N,K]
// ---------------------------------------------------------------------------
__global__ void wsplit_kernel(const float* __restrict__ W) {
    __shared__ float tile[32][33];
    int n0 = blockIdx.x * 32, k0 = blockIdx.y * 32;
    int tx = threadIdx.x, ty = threadIdx.y;
    for (int r = ty; r < 32; r += 8)
        tile[r][tx] = W[(size_t)(k0 + r) * DM + n0 + tx];
    __syncthreads();
    for (int r = ty; r < 32; r += 8) {
        float v = tile[tx][r];                 // = W[k0+tx][n0+r]
        __nv_bfloat16 h = __float2bfloat16(v);
        __nv_bfloat16 l = __float2bfloat16(v - __bfloat162float(h));
        g_Bh[(size_t)(n0 + r) * DM + k0 + tx] = h;
        g_Bl[(size_t)(n0 + r) * DM + k0 + tx] = l;
    }
}

// ---------------------------------------------------------------------------
// Prep C: va[b,:] = (acoustic[b,:] @ Wa + ba) @ Wv + bv
// ---------------------------------------------------------------------------
__global__ void va_kernel(const float* __restrict__ ac,
                          const float* __restrict__ Wa,
                          const float* __restrict__ ba,
                          const float* __restrict__ Wv,
                          const float* __restrict__ bv) {
    __shared__ float fa[DM];
    __shared__ float acs[DAUD];
    const int b = blockIdx.x;
    const int t = threadIdx.x;
    if (t < DAUD) acs[t] = ac[b * DAUD + t];
    __syncthreads();
    float v = ba[t];
#pragma unroll
    for (int k = 0; k < DAUD; k++) v += acs[k] * Wa[k * DM + t];
    fa[t] = v;
    __syncthreads();
    float o = bv[t];
    for (int e = 0; e < DM; e++) o += fa[e] * Wv[e * DM + t];
    g_va[b * DM + t] = o;
}

// ---------------------------------------------------------------------------
// GEMM: CTA tile 256x128, 512 threads (16 warps, 4x4), warp tile 64x32.
// KT=64 chunks, 2-stage cp.async ring, SW128 smem.
// ---------------------------------------------------------------------------
#define BM      256
#define BN      128
#define KT      64
#define KSTEPS  4
#define NCHUNK  (DM / KT)                 // 12
#define TILE_A  (BM * 128)                // 32 KB (256 rows x 128B)
#define TILE_B  (BN * 128)                // 16 KB
#define STAGEB  (2 * TILE_A + 2 * TILE_B) // 96 KB
#define SMEM_DYN (2 * STAGEB + 1024)

__device__ __forceinline__ void load_chunk(uint32_t stg,
                                           const __nv_bfloat16* const* g0,
                                           int k0, int tid) {
    // A tiles: 2048 x 16B each, 4 iters/thread
#pragma unroll
    for (int t = 0; t < 2; t++) {
        const uint32_t tb = stg + t * TILE_A;
#pragma unroll
        for (int j = 0; j < 4; j++) {
            const int q = tid + j * 512;          // 0..2047
            const int row = q >> 3, cc = q & 7;
            cpasync16(tb + SWZ(row * 128 + cc * 16),
                      g0[t] + (size_t)row * DM + k0 + cc * 8);
        }
    }
    // B tiles: 1024 x 16B each, 2 iters/thread
#pragma unroll
    for (int t = 0; t < 2; t++) {
        const uint32_t tb = stg + 2 * TILE_A + t * TILE_B;
#pragma unroll
        for (int j = 0; j < 2; j++) {
            const int q = tid + j * 512;          // 0..1023
            const int row = q >> 3, cc = q & 7;
            cpasync16(tb + SWZ(row * 128 + cc * 16),
                      g0[2 + t] + (size_t)row * DM + k0 + cc * 8);
        }
    }
    asm volatile("cp.async.commit_group;");
}

__global__ __launch_bounds__(512, 1)
void gemm_kernel(const float* __restrict__ bias, float* __restrict__ out) {
    extern __shared__ char dynsmem[];
    uint32_t base = smem_u32(dynsmem);
    base = (base + 1023u) & ~1023u;

    const int tid = threadIdx.x;
    const int wid = tid >> 5, lane = tid & 31;
    const int wm = wid >> 2, wn = wid & 3;   // 4x4 warp grid
    const int bn = blockIdx.x, bm = blockIdx.y;

    const __nv_bfloat16* g0[4] = {
        g_Ah + (size_t)bm * BM * DM,
        g_Al + (size_t)bm * BM * DM,
        g_Bh + (size_t)bn * BN * DM,
        g_Bl + (size_t)bn * BN * DM };

    float acc[4][4][4] = {};

    load_chunk(base + 0 * STAGEB, g0, 0 * KT, tid);
    load_chunk(base + 1 * STAGEB, g0, 1 * KT, tid);

    for (int c = 0; c < NCHUNK; ++c) {
        asm volatile("cp.async.wait_group 1;");
        __syncthreads();

        const uint32_t stg = base + (c & 1) * STAGEB;
        const uint32_t Ah = stg,                 Al = stg + TILE_A;
        const uint32_t Bh = stg + 2 * TILE_A,    Bl = Bh + TILE_B;

#pragma unroll
        for (int ks = 0; ks < KSTEPS; ks++) {
            uint32_t ah[4][4], al[4][4];
            const int akb = ks * 32 + (lane >> 4) * 16;
#pragma unroll
            for (int mt = 0; mt < 4; mt++) {
                const int row = wm * 64 + mt * 16 + (lane & 15);
                const uint32_t off = SWZ(row * 128 + akb);
                ldsm4(ah[mt], Ah + off);
                ldsm4(al[mt], Al + off);
            }
            const int brow_base = wn * 32 + (lane & 7) + ((lane >> 4) << 3);
            const int bkb = ks * 32 + ((lane >> 3) & 1) * 16;
#pragma unroll
            for (int p = 0; p < 2; p++) {
                uint32_t bh[4], bl[4];
                const uint32_t off = SWZ((brow_base + p * 16) * 128 + bkb);
                ldsm4(bh, Bh + off);
                ldsm4(bl, Bl + off);
                // Product-major issue order: 8 independent MMAs between
                // consecutive writes to the same accumulator (RAW distance
                // 2 -> 8), covering HMMA result latency.
#pragma unroll
                for (int mt = 0; mt < 4; mt++) {       // A_hi * B_hi
                    mma16816(acc[mt][2 * p],     ah[mt], bh[0], bh[1]);
                    mma16816(acc[mt][2 * p + 1], ah[mt], bh[2], bh[3]);
                }
#pragma unroll
                for (int mt = 0; mt < 4; mt++) {       // A_hi * B_lo
                    mma16816(acc[mt][2 * p],     ah[mt], bl[0], bl[1]);
                    mma16816(acc[mt][2 * p + 1], ah[mt], bl[2], bl[3]);
                }
#pragma unroll
                for (int mt = 0; mt < 4; mt++) {       // A_lo * B_hi
                    mma16816(acc[mt][2 * p],     al[mt], bh[0], bh[1]);
                    mma16816(acc[mt][2 * p + 1], al[mt], bh[2], bh[3]);
                }
            }
        }
        __syncthreads();
        if (c + 2 < NCHUNK)
            load_chunk(stg, g0, (c + 2) * KT, tid);
        else
            asm volatile("cp.async.commit_group;");   // keep group count in step
    }

    // Epilogue: out = acc + bias + va[b].  BM=256 -> bidx = bm >> 3.
    const int bidx = bm >> 3;
#pragma unroll
    for (int mt = 0; mt < 4; mt++) {
        const int r0 = bm * BM + wm * 64 + mt * 16 + (lane >> 2);
#pragma unroll
        for (int nt = 0; nt < 4; nt++) {
            const int col = bn * BN + wn * 32 + nt * 8 + (lane & 3) * 2;
            const float bv0 = bias[col]     + g_va[bidx * DM + col];
            const float bv1 = bias[col + 1] + g_va[bidx * DM + col + 1];
            float2 v0, v1;
            v0.x = acc[mt][nt][0] + bv0;  v0.y = acc[mt][nt][1] + bv1;
            v1.x = acc[mt][nt][2] + bv0;  v1.y = acc[mt][nt][3] + bv1;
            *(float2*)(out + (size_t)r0 * DM + col)       = v0;
            *(float2*)(out + (size_t)(r0 + 8) * DM + col) = v1;
        }
    }
}

// ---------------------------------------------------------------------------
// Launch. Input order: text, acoustic, Wt, bt, Wa, ba, Wq,bq, Wk,bk, Wv,bv
// ---------------------------------------------------------------------------
extern "C" void kernel_launch(void* const* d_in, const int* in_sizes, int n_in,
                              void* d_out, int out_size) {
    const float* text = (const float*)d_in[0];
    const float* ac   = (const float*)d_in[1];
    const float* Wt   = (const float*)d_in[2];
    const float* bt   = (const float*)d_in[3];
    const float* Wa   = (const float*)d_in[4];
    const float* ba   = (const float*)d_in[5];
    const float* Wv   = (const float*)d_in[10];
    const float* bv   = (const float*)d_in[11];
    float* out = (float*)d_out;

    cudaFuncSetAttribute(gemm_kernel,
                         cudaFuncAttributeMaxDynamicSharedMemorySize, SMEM_DYN);

    split_text_kernel<<<(M_TOT * DM) / 8 / 256, 256>>>(text);
    wsplit_kernel<<<dim3(DM / 32, DM / 32), dim3(32, 8)>>>(Wt);
    va_kernel<<<BATCH, DM>>>(ac, Wa, ba, Wv, bv);

    gemm_kernel<<<dim3(DM / BN, M_TOT / BM), 512, SMEM_DYN>>>(bt, out);
}